// round 14
// baseline (speedup 1.0000x reference)
#include <cuda_runtime.h>
#include <cuda_bf16.h>

// AngleTensor: out[b,i,j,k] = mask * acos( u_j . u_k ), u_t = (p_t-p_i)/|p_t-p_i|
// R13: mask-free hot loop (stores raw acos everywhere; ~8 fewer issue slots
// per 4-elem iter), then a tiny epilogue overwrites the masked set -- row i,
// column i, diagonal (384 of 16384 elements) -- with exact zeros after
// __syncthreads. Restores exact diagonal zeros too.

#define AT_N 128

__device__ __forceinline__ float sqapx(float x) {
    float s; asm("sqrt.approx.f32 %0, %1;" : "=f"(s) : "f"(x)); return s;
}

// unmasked acos, ~11 issued ops (A&S 4.4.45, branchless reflect)
__device__ __forceinline__ float ang(float ux, float uy, float uz,
                                     const float4 k) {
    float c  = fmaf(uz, k.z, fmaf(uy, k.y, ux * k.x));
    float ax = fabsf(c);
    float y  = fmaf(ax, -1.0f, 1.0f);                      // >= -3e-7
    float s  = sqapx(fabsf(y));                            // abs folds in MUFU
    float p  = fmaf(fmaf(fmaf(ax, -0.0187293f, 0.0742610f),
                         ax, -0.2121144f), ax, 1.5707288f);
    float sg = __uint_as_float((__float_as_uint(c) & 0x80000000u)
                               | 0x3f800000u);
    return fmaf(sg, fmaf(s, p, -1.57079632679f), 1.57079632679f);
}

__global__ __launch_bounds__(256, 6)
void AngleTensor_69767448756825_kernel(const float* __restrict__ pos,
                                       float* __restrict__ out) {
    const int i    = blockIdx.x;
    const int b    = blockIdx.y;
    const int t    = threadIdx.x;
    const int lane = t & 31;
    const int w    = t >> 5;

    __shared__ float4 su[AT_N];   // {ux, uy, uz, 0}

    const float* pb = pos + (size_t)b * AT_N * 3;
    const float pix = pb[i * 3 + 0];
    const float piy = pb[i * 3 + 1];
    const float piz = pb[i * 3 + 2];

    if (t < AT_N) {
        float dx = pb[t * 3 + 0] - pix;
        float dy = pb[t * 3 + 1] - piy;
        float dz = pb[t * 3 + 2] - piz;
        float n2 = dx * dx + dy * dy + dz * dz;
        float inv = (n2 > 0.0f) ? rsqrtf(n2) : 0.0f;   // t==i -> zero vector
        su[t] = make_float4(dx * inv, dy * inv, dz * inv, 0.0f);
    }
    __syncthreads();

    // Lane-owned k-quad (xyz only) for all rows.
    const int k0 = lane << 2;
    const float4 q0 = su[k0 + 0];
    const float4 q1 = su[k0 + 1];
    const float4 q2 = su[k0 + 2];
    const float4 q3 = su[k0 + 3];

    float* otile = out + ((size_t)b * AT_N + i) * AT_N * AT_N;

    // Hoisted bases: loop body uses only immediate offsets.
    const float4* jrow = su + w * 16;
    float4* ostart = reinterpret_cast<float4*>(otile) + w * 16 * 32 + lane;

    // Mask-free hot loop: LDS.128[imm] + 44 fp32 ops + STG.128[imm].
    #pragma unroll
    for (int it = 0; it < 16; ++it) {
        const float4 uj = jrow[it];

        float4 r4;
        r4.x = ang(uj.x, uj.y, uj.z, q0);
        r4.y = ang(uj.x, uj.y, uj.z, q1);
        r4.z = ang(uj.x, uj.y, uj.z, q2);
        r4.w = ang(uj.x, uj.y, uj.z, q3);

        ostart[it * 32] = r4;
    }

    // Order bulk stores before the fix-up overwrites (block-scope fence+sync).
    __syncthreads();

    // Epilogue: exact zeros on the masked set (row i, column i, diagonal).
    if (t < 32) {
        reinterpret_cast<float4*>(otile + i * AT_N)[t] =
            make_float4(0.f, 0.f, 0.f, 0.f);               // row i
    }
    if (t < AT_N) {
        otile[t * AT_N + i]  = 0.0f;                       // column i
        otile[t * AT_N + t]  = 0.0f;                       // diagonal
    }
}

extern "C" void kernel_launch(void* const* d_in, const int* in_sizes, int n_in,
                              void* d_out, int out_size) {
    const int B = out_size / (AT_N * AT_N * AT_N);

    const float* pos = nullptr;
    for (int a = 0; a < n_in; ++a)
        if (in_sizes[a] == B * AT_N * 3) pos = (const float*)d_in[a];
    if (!pos) pos = (const float*)d_in[0];

    dim3 grid(AT_N, B);
    AngleTensor_69767448756825_kernel<<<grid, 256>>>(pos, (float*)d_out);
}

// round 15
// speedup vs baseline: 1.0568x; 1.0568x over previous
#include <cuda_runtime.h>
#include <cuda_bf16.h>

// AngleTensor: out[b,i,j,k] = mask * acos( u_j . u_k ), u_t = (p_t-p_i)/|p_t-p_i|
// R14 = R12 body (fully unrolled, immediate-offset, branch-free) +
// __launch_bounds__(256,7): 148 SMs x 7 blocks = 1036 >= 1024 grid -> the
// ENTIRE grid is resident in one wave (occ 6 left a 136-block straggler wave
// that ran ~alone per SM and capped aggregate issue at 75%).

#define AT_N 128

__device__ __forceinline__ float sqapx(float x) {
    float s; asm("sqrt.approx.f32 %0, %1;" : "=f"(s) : "f"(x)); return s;
}

// masked acos. m = wj*wk (0/1); masked entries end exactly 0 (c=+-0 -> r~pi/2
// -> *0); diagonal j==k by value (|err| <= 7e-4 on 0.8% of elements).
// nhp = -pi/2 register; +pi/2 comes from the free negation modifier.
__device__ __forceinline__ float ang(float ux, float uy, float uz,
                                     const float4 k, float m, float nhp) {
    float c  = fmaf(uz, k.z, fmaf(uy, k.y, ux * k.x));
    float ax = fabsf(c);
    float y  = fmaf(ax, -1.0f, 1.0f);                    // >= -3e-7
    float s  = sqapx(fabsf(y));
    float p  = fmaf(fmaf(fmaf(ax, -0.0187293f, 0.0742610f),
                         ax, -0.2121144f), ax, 1.5707288f); // A&S 4.4.45
    float sg = __uint_as_float((__float_as_uint(c) & 0x80000000u)
                               | 0x3f800000u);
    float r  = fmaf(sg, fmaf(s, p, nhp), -nhp);          // -nhp = +pi/2 (free)
    return r * m;
}

__global__ __launch_bounds__(256, 7)
void AngleTensor_69767448756825_kernel(const float* __restrict__ pos,
                                       float* __restrict__ out) {
    const int i    = blockIdx.x;
    const int b    = blockIdx.y;
    const int t    = threadIdx.x;
    const int lane = t & 31;
    const int w    = t >> 5;

    __shared__ float4 su[AT_N];   // {ux, uy, uz, weight(t!=i)}

    const float* pb = pos + (size_t)b * AT_N * 3;
    const float pix = pb[i * 3 + 0];
    const float piy = pb[i * 3 + 1];
    const float piz = pb[i * 3 + 2];

    if (t < AT_N) {
        float dx = pb[t * 3 + 0] - pix;
        float dy = pb[t * 3 + 1] - piy;
        float dz = pb[t * 3 + 2] - piz;
        float n2 = dx * dx + dy * dy + dz * dz;
        float inv = (n2 > 0.0f) ? rsqrtf(n2) : 0.0f;   // t==i -> zero vector
        float wt  = (t == i) ? 0.0f : 1.0f;
        su[t] = make_float4(dx * inv, dy * inv, dz * inv, wt);
    }
    __syncthreads();

    // Lane-owned k-quad (16 regs) for all rows.
    const int k0 = lane << 2;
    const float4 q0 = su[k0 + 0];
    const float4 q1 = su[k0 + 1];
    const float4 q2 = su[k0 + 2];
    const float4 q3 = su[k0 + 3];

    const float nhp = -1.57079632679f;

    // Hoisted bases: loop body uses only immediate offsets.
    const float4* jrow = su + w * 16;
    float4* ostart = reinterpret_cast<float4*>(
        out + ((size_t)b * AT_N + i) * AT_N * AT_N) + w * 16 * 32 + lane;

    #pragma unroll
    for (int it = 0; it < 16; ++it) {
        const float4 uj = jrow[it];                      // LDS.128 [R+imm]

        float4 r4;
        r4.x = ang(uj.x, uj.y, uj.z, q0, uj.w * q0.w, nhp);
        r4.y = ang(uj.x, uj.y, uj.z, q1, uj.w * q1.w, nhp);
        r4.z = ang(uj.x, uj.y, uj.z, q2, uj.w * q2.w, nhp);
        r4.w = ang(uj.x, uj.y, uj.z, q3, uj.w * q3.w, nhp);

        ostart[it * 32] = r4;                            // STG.128 [R+imm]
    }
}

extern "C" void kernel_launch(void* const* d_in, const int* in_sizes, int n_in,
                              void* d_out, int out_size) {
    const int B = out_size / (AT_N * AT_N * AT_N);

    const float* pos = nullptr;
    for (int a = 0; a < n_in; ++a)
        if (in_sizes[a] == B * AT_N * 3) pos = (const float*)d_in[a];
    if (!pos) pos = (const float*)d_in[0];

    dim3 grid(AT_N, B);
    AngleTensor_69767448756825_kernel<<<grid, 256>>>(pos, (float*)d_out);
}

// round 16
// speedup vs baseline: 1.0856x; 1.0272x over previous
#include <cuda_runtime.h>
#include <cuda_bf16.h>

// AngleTensor: out[b,i,j,k] = mask * acos( u_j . u_k ), u_t = (p_t-p_i)/|p_t-p_i|
// R15 = R12 body with a 13-instruction element (was 15):
//  - k-mask folded into sqrt arg: y = wk*(1-ax) >= 0 exactly (no |y| op),
//    with per-lane pre-masked reflect offsets nhp_k = -pi/2*wk so masked k
//    yields exactly 0 even for c = -0 (signed-zero proof).
//  - ax = fminf(|c|,1) -> single FMNMX with free abs modifier.
//  - row mask stays as one FMUL (x wj) -- mandatory per R5's 8e-2 failure.

#define AT_N 128

__device__ __forceinline__ float sqapx(float x) {
    float s; asm("sqrt.approx.f32 %0, %1;" : "=f"(s) : "f"(x)); return s;
}

// 13 issued ops. wk in {0,1}, nhpk = -pi/2*wk, wj in {0,1}.
__device__ __forceinline__ float ang(float ux, float uy, float uz,
                                     const float4 k, float wk, float nhpk,
                                     float wj) {
    float c  = fmaf(uz, k.z, fmaf(uy, k.y, ux * k.x));   // 3
    float ax = fminf(fabsf(c), 1.0f);                    // 1 FMNMX(|c|)
    float y  = fmaf(ax, -wk, wk);                        // 1: wk*(1-ax) >= 0
    float s  = sqapx(y);                                 // 1 MUFU
    float p  = fmaf(fmaf(fmaf(ax, -0.0187293f, 0.0742610f),
                         ax, -0.2121144f), ax, 1.5707288f);  // 3 (A&S 4.4.45)
    float sg = __uint_as_float((__float_as_uint(c) & 0x80000000u)
                               | 0x3f800000u);           // 1 LOP3
    float r  = fmaf(sg, fmaf(s, p, nhpk), -nhpk);        // 2 (free neg)
    return r * wj;                                       // 1
}

__global__ __launch_bounds__(256, 6)
void AngleTensor_69767448756825_kernel(const float* __restrict__ pos,
                                       float* __restrict__ out) {
    const int i    = blockIdx.x;
    const int b    = blockIdx.y;
    const int t    = threadIdx.x;
    const int lane = t & 31;
    const int w    = t >> 5;

    __shared__ float4 su[AT_N];   // {ux, uy, uz, weight(t!=i)}

    const float* pb = pos + (size_t)b * AT_N * 3;
    const float pix = pb[i * 3 + 0];
    const float piy = pb[i * 3 + 1];
    const float piz = pb[i * 3 + 2];

    if (t < AT_N) {
        float dx = pb[t * 3 + 0] - pix;
        float dy = pb[t * 3 + 1] - piy;
        float dz = pb[t * 3 + 2] - piz;
        float n2 = dx * dx + dy * dy + dz * dz;
        float inv = (n2 > 0.0f) ? rsqrtf(n2) : 0.0f;   // t==i -> zero vector
        float wt  = (t == i) ? 0.0f : 1.0f;
        su[t] = make_float4(dx * inv, dy * inv, dz * inv, wt);
    }
    __syncthreads();

    // Lane-owned k-quad + per-lane mask weights and pre-masked offsets.
    const int k0 = lane << 2;
    const float4 q0 = su[k0 + 0];
    const float4 q1 = su[k0 + 1];
    const float4 q2 = su[k0 + 2];
    const float4 q3 = su[k0 + 3];
    const float n0 = -1.57079632679f * q0.w;
    const float n1 = -1.57079632679f * q1.w;
    const float n2 = -1.57079632679f * q2.w;
    const float n3 = -1.57079632679f * q3.w;

    // Hoisted bases: loop body uses only immediate offsets.
    const float4* jrow = su + w * 16;
    float4* ostart = reinterpret_cast<float4*>(
        out + ((size_t)b * AT_N + i) * AT_N * AT_N) + w * 16 * 32 + lane;

    #pragma unroll
    for (int it = 0; it < 16; ++it) {
        const float4 uj = jrow[it];                      // LDS.128 [R+imm]

        float4 r4;
        r4.x = ang(uj.x, uj.y, uj.z, q0, q0.w, n0, uj.w);
        r4.y = ang(uj.x, uj.y, uj.z, q1, q1.w, n1, uj.w);
        r4.z = ang(uj.x, uj.y, uj.z, q2, q2.w, n2, uj.w);
        r4.w = ang(uj.x, uj.y, uj.z, q3, q3.w, n3, uj.w);

        ostart[it * 32] = r4;                            // STG.128 [R+imm]
    }
}

extern "C" void kernel_launch(void* const* d_in, const int* in_sizes, int n_in,
                              void* d_out, int out_size) {
    const int B = out_size / (AT_N * AT_N * AT_N);

    const float* pos = nullptr;
    for (int a = 0; a < n_in; ++a)
        if (in_sizes[a] == B * AT_N * 3) pos = (const float*)d_in[a];
    if (!pos) pos = (const float*)d_in[0];

    dim3 grid(AT_N, B);
    AngleTensor_69767448756825_kernel<<<grid, 256>>>(pos, (float*)d_out);
}